// round 1
// baseline (speedup 1.0000x reference)
#include <cuda_runtime.h>
#include <math.h>

#define NBIN 25
#define BATCH 16
#define NROWS 50000
#define MDIM 128
#define BLOCKS_PER_B 48
#define WARPS_PER_BLOCK 8
#define INV_DELTA 12.0f   // 1/DELTA, DELTA = 2/(NBIN-1)

// Global scratch (allocation-free per harness rules)
__device__ double g_num[BATCH][NBIN];
__device__ double g_den[BATCH][NBIN];
__device__ double g_lab[BATCH];

__global__ void zero_kernel() {
    int i = threadIdx.x;
    // BATCH*NBIN = 400 entries each
    for (int k = i; k < BATCH * NBIN; k += blockDim.x) {
        ((double*)g_num)[k] = 0.0;
        ((double*)g_den)[k] = 0.0;
    }
    if (i < BATCH) g_lab[i] = 0.0;
}

__global__ __launch_bounds__(256) void qap_main(
    const float* __restrict__ qX,
    const float* __restrict__ dXs,
    const int*   __restrict__ labels)
{
    const int b    = blockIdx.y;
    const int tid  = threadIdx.x;
    const int lane = tid & 31;
    const int warpId = tid >> 5;

    __shared__ double s_num[NBIN];
    __shared__ double s_den[NBIN];
    __shared__ double s_lab;

    if (tid < NBIN) { s_num[tid] = 0.0; s_den[tid] = 0.0; }
    if (tid == 0)   s_lab = 0.0;

    // Each lane owns 4 consecutive floats of qX[b]; also compute qn redundantly per warp.
    const float4 qv = reinterpret_cast<const float4*>(qX + b * MDIM)[lane];
    float qs = qv.x*qv.x + qv.y*qv.y + qv.z*qv.z + qv.w*qv.w;
    #pragma unroll
    for (int o = 16; o; o >>= 1) qs += __shfl_xor_sync(0xffffffffu, qs, o);
    const float qn = fmaxf(sqrtf(qs), 1e-8f);

    __syncthreads();

    const float* base = dXs + (size_t)b * NROWS * MDIM;
    const int*   labBase = labels + (size_t)b * NROWS;

    const int warpGlobal = blockIdx.x * WARPS_PER_BLOCK + warpId;
    const int warpStride = BLOCKS_PER_B * WARPS_PER_BLOCK;
    const int nQuads = NROWS / 4;   // 50000 divisible by 4

    float labAcc = 0.0f;

    for (int q = warpGlobal; q < nQuads; q += warpStride) {
        const int n0 = q * 4;
        float d[4], s[4];
        #pragma unroll
        for (int r = 0; r < 4; r++) {
            const float4 v = reinterpret_cast<const float4*>(
                base + (size_t)(n0 + r) * MDIM)[lane];
            d[r] = v.x*qv.x + v.y*qv.y + v.z*qv.z + v.w*qv.w;
            s[r] = v.x*v.x  + v.y*v.y  + v.z*v.z  + v.w*v.w;
        }
        #pragma unroll
        for (int o = 16; o; o >>= 1) {
            #pragma unroll
            for (int r = 0; r < 4; r++) {
                d[r] += __shfl_xor_sync(0xffffffffu, d[r], o);
                s[r] += __shfl_xor_sync(0xffffffffu, s[r], o);
            }
        }
        if (lane < 4) {
            const int lab = labBase[n0 + lane];
            labAcc += (float)lab;
            const float dn  = fmaxf(sqrtf(s[lane]), 1e-8f);
            const float sim = d[lane] / (qn * dn);
            const float t   = (1.0f - sim) * INV_DELTA;
            const int m0 = (int)floorf(t);
            #pragma unroll
            for (int j = 0; j < 2; j++) {
                const int m = m0 + j;
                if (m >= 0 && m < NBIN) {
                    const float w = 1.0f - fabsf(t - (float)m);
                    if (w > 0.0f) {
                        atomicAdd(&s_den[m], (double)w);
                        if (lab) atomicAdd(&s_num[m], (double)w);
                    }
                }
            }
        }
    }

    // Reduce label count across warp (only lanes 0-3 hold nonzero values)
    #pragma unroll
    for (int o = 16; o; o >>= 1) labAcc += __shfl_xor_sync(0xffffffffu, labAcc, o);
    if (lane == 0 && labAcc != 0.0f) atomicAdd(&s_lab, (double)labAcc);

    __syncthreads();

    if (tid < NBIN) {
        if (s_num[tid] != 0.0) atomicAdd(&g_num[b][tid], s_num[tid]);
        if (s_den[tid] != 0.0) atomicAdd(&g_den[b][tid], s_den[tid]);
    }
    if (tid == 0) atomicAdd(&g_lab[b], s_lab);
}

__global__ void finalize_kernel(float* __restrict__ out) {
    const int b = threadIdx.x;
    __shared__ double s_ap[BATCH];
    if (b < BATCH) {
        const double lab = g_lab[b];
        double cn = 0.0, cd = 0.0, ap = 0.0;
        #pragma unroll
        for (int m = 0; m < NBIN; m++) {
            const double num = g_num[b][m];
            const double den = g_den[b][m];
            cn += num;
            cd += den;
            const double precision = cn / (1e-16 + cd);
            const double recall    = num / lab;
            ap += precision * recall;
        }
        s_ap[b] = ap;
    }
    __syncthreads();
    if (b == 0) {
        double sum = 0.0;
        #pragma unroll
        for (int i = 0; i < BATCH; i++) sum += s_ap[i];
        out[0] = (float)(sum / (double)BATCH);
    }
}

extern "C" void kernel_launch(void* const* d_in, const int* in_sizes, int n_in,
                              void* d_out, int out_size) {
    const float* qX     = (const float*)d_in[0];
    const float* dXs    = (const float*)d_in[1];
    const int*   labels = (const int*)d_in[2];
    float*       out    = (float*)d_out;

    zero_kernel<<<1, 256>>>();
    dim3 grid(BLOCKS_PER_B, BATCH);
    qap_main<<<grid, 256>>>(qX, dXs, labels);
    finalize_kernel<<<1, 32>>>(out);
}

// round 2
// speedup vs baseline: 1.9609x; 1.9609x over previous
#include <cuda_runtime.h>
#include <math.h>

#define NBIN 25
#define BATCH 16
#define NROWS 50000
#define MDIM 128
#define BLOCKS_PER_B 48
#define NBLOCKS (BATCH * BLOCKS_PER_B)
#define WARPS_PER_BLOCK 8
#define NVALS (2 * NBIN + 1)          // 25 den, 25 num, 1 label-sum
#define INV_DELTA 12.0f               // 1/DELTA, DELTA = 2/(NBIN-1)

// Per-block partial results (overwritten every launch; no zeroing needed).
__device__ double g_part[BATCH][BLOCKS_PER_B][NVALS];
__device__ unsigned int g_done = 0;   // reset to 0 by the last block each launch

__global__ __launch_bounds__(256) void qap_fused(
    const float* __restrict__ qX,
    const float* __restrict__ dXs,
    const int*   __restrict__ labels,
    float*       __restrict__ out)
{
    const int b    = blockIdx.y;
    const int tid  = threadIdx.x;
    const int lane = tid & 31;
    const int w    = tid >> 5;
    const int g    = lane >> 3;   // row within quad (0..3)
    const int l    = lane & 7;    // chunk owner within row (0..7)

    // Per-warp bins, padded stride 33 so different warps land on different banks.
    __shared__ float sbin[WARPS_PER_BLOCK][2][33];   // [warp][den/num][bin]
    __shared__ float slab[WARPS_PER_BLOCK];
    for (int i = tid; i < WARPS_PER_BLOCK * 2 * 33; i += 256)
        ((float*)sbin)[i] = 0.0f;
    if (tid < WARPS_PER_BLOCK) slab[tid] = 0.0f;
    __syncthreads();

    // q chunks: lane owns float4 indices {l, l+8, l+16, l+24} of qX[b]
    const float4* q4 = reinterpret_cast<const float4*>(qX + b * MDIM);
    const float4 q0 = q4[l], q1 = q4[l + 8], q2 = q4[l + 16], q3 = q4[l + 24];
    float qs = q0.x*q0.x + q0.y*q0.y + q0.z*q0.z + q0.w*q0.w
             + q1.x*q1.x + q1.y*q1.y + q1.z*q1.z + q1.w*q1.w
             + q2.x*q2.x + q2.y*q2.y + q2.z*q2.z + q2.w*q2.w
             + q3.x*q3.x + q3.y*q3.y + q3.z*q3.z + q3.w*q3.w;
    qs += __shfl_xor_sync(0xffffffffu, qs, 4);
    qs += __shfl_xor_sync(0xffffffffu, qs, 2);
    qs += __shfl_xor_sync(0xffffffffu, qs, 1);
    const float qn = fmaxf(sqrtf(qs), 1e-8f);

    const float* base = dXs + (size_t)b * NROWS * MDIM;
    const int*   labB = labels + (size_t)b * NROWS;

    const int warpGlobal = blockIdx.x * WARPS_PER_BLOCK + w;
    const int warpStride = BLOCKS_PER_B * WARPS_PER_BLOCK;
    const int nQuads = NROWS / 4;

    float labAcc = 0.0f;
    float* const db = sbin[w][0];
    float* const nb = sbin[w][1];

    #pragma unroll 2
    for (int q = warpGlobal; q < nQuads; q += warpStride) {
        const int n0 = q * 4;
        // label load first — overlaps the 4 wide row loads below
        const int lab = labB[n0 + g];

        const float4* r4 = reinterpret_cast<const float4*>(
            base + (size_t)(n0 + g) * MDIM);
        const float4 v0 = r4[l], v1 = r4[l + 8], v2 = r4[l + 16], v3 = r4[l + 24];

        float d = v0.x*q0.x + v0.y*q0.y + v0.z*q0.z + v0.w*q0.w;
        d      += v1.x*q1.x + v1.y*q1.y + v1.z*q1.z + v1.w*q1.w;
        d      += v2.x*q2.x + v2.y*q2.y + v2.z*q2.z + v2.w*q2.w;
        d      += v3.x*q3.x + v3.y*q3.y + v3.z*q3.z + v3.w*q3.w;
        float s = v0.x*v0.x + v0.y*v0.y + v0.z*v0.z + v0.w*v0.w;
        s      += v1.x*v1.x + v1.y*v1.y + v1.z*v1.z + v1.w*v1.w;
        s      += v2.x*v2.x + v2.y*v2.y + v2.z*v2.z + v2.w*v2.w;
        s      += v3.x*v3.x + v3.y*v3.y + v3.z*v3.z + v3.w*v3.w;

        // reduce within the 8-lane group (3 stages x 2 values = 6 shuffles)
        d += __shfl_xor_sync(0xffffffffu, d, 4);
        s += __shfl_xor_sync(0xffffffffu, s, 4);
        d += __shfl_xor_sync(0xffffffffu, d, 2);
        s += __shfl_xor_sync(0xffffffffu, s, 2);
        d += __shfl_xor_sync(0xffffffffu, d, 1);
        s += __shfl_xor_sync(0xffffffffu, s, 1);

        if (l == 0) {
            labAcc += (float)lab;
            const float dn  = fmaxf(sqrtf(s), 1e-8f);
            const float sim = __fdividef(d, qn * dn);
            const float t   = (1.0f - sim) * INV_DELTA;
            const float fm  = floorf(t);
            const int   m0  = (int)fm;
            const float frac = t - fm;
            if ((unsigned)m0 < NBIN) {
                atomicAdd(&db[m0], 1.0f - frac);
                if (lab) atomicAdd(&nb[m0], 1.0f - frac);
            }
            const int m1 = m0 + 1;
            if ((unsigned)m1 < NBIN && frac > 0.0f) {
                atomicAdd(&db[m1], frac);
                if (lab) atomicAdd(&nb[m1], frac);
            }
        }
    }

    // label sum: only lanes with l==0 are nonzero; xor 8,16 pairs them together
    labAcc += __shfl_xor_sync(0xffffffffu, labAcc, 8);
    labAcc += __shfl_xor_sync(0xffffffffu, labAcc, 16);
    if (lane == 0) slab[w] = labAcc;
    __syncthreads();

    // Block epilogue: reduce 8 warp arrays -> per-block double partials
    double* part = g_part[b][blockIdx.x];
    if (tid < NBIN) {
        double acc = 0.0;
        #pragma unroll
        for (int k = 0; k < WARPS_PER_BLOCK; k++) acc += (double)sbin[k][0][tid];
        part[tid] = acc;
    } else if (tid < 2 * NBIN) {
        const int m = tid - NBIN;
        double acc = 0.0;
        #pragma unroll
        for (int k = 0; k < WARPS_PER_BLOCK; k++) acc += (double)sbin[k][1][m];
        part[tid] = acc;
    } else if (tid == 2 * NBIN) {
        double acc = 0.0;
        #pragma unroll
        for (int k = 0; k < WARPS_PER_BLOCK; k++) acc += (double)slab[k];
        part[2 * NBIN] = acc;
    }
    __threadfence();
    __syncthreads();

    __shared__ bool isLast;
    if (tid == 0) {
        const unsigned v = atomicAdd(&g_done, 1u);
        isLast = (v == NBLOCKS - 1);
    }
    __syncthreads();
    if (!isLast) return;
    __threadfence();

    // ---- Finalize in the last block ----
    __shared__ double sred[BATCH][NVALS];
    for (int i = tid; i < BATCH * NVALS; i += 256) {
        const int bb = i / NVALS;
        const int vv = i % NVALS;
        double acc = 0.0;
        for (int k = 0; k < BLOCKS_PER_B; k++) acc += g_part[bb][k][vv];
        sred[bb][vv] = acc;
    }
    __syncthreads();

    __shared__ double sap[BATCH];
    if (tid < BATCH) {
        const double lab = sred[tid][2 * NBIN];
        double cn = 0.0, cd = 0.0, ap = 0.0;
        #pragma unroll
        for (int m = 0; m < NBIN; m++) {
            const double den = sred[tid][m];          // sum of sa
            const double num = sred[tid][NBIN + m];   // sum of sa*label
            cn += num;                                 // pDen
            cd += den;                                 // pNum - eps
            const double precision = cn / (1e-16 + cd);
            const double recall    = num / lab;
            ap += precision * recall;
        }
        sap[tid] = ap;
    }
    __syncthreads();
    if (tid == 0) {
        double ssum = 0.0;
        #pragma unroll
        for (int i = 0; i < BATCH; i++) ssum += sap[i];
        out[0] = (float)(ssum / (double)BATCH);
        g_done = 0;   // reset for next graph replay (deterministic)
    }
}

extern "C" void kernel_launch(void* const* d_in, const int* in_sizes, int n_in,
                              void* d_out, int out_size) {
    const float* qX     = (const float*)d_in[0];
    const float* dXs    = (const float*)d_in[1];
    const int*   labels = (const int*)d_in[2];
    float*       out    = (float*)d_out;

    dim3 grid(BLOCKS_PER_B, BATCH);
    qap_fused<<<grid, 256>>>(qX, dXs, labels, out);
}